// round 17
// baseline (speedup 1.0000x reference)
#include <cuda_runtime.h>
#include <cuda_fp16.h>
#include <cstdint>

// ============================================================================
// GroupedExperts: out = swiglu(x@W1+b1) @ W2 + b2   (E=8, T=2048, D=2048)
// R17: single fused GEMM1+GEMM2 launch. Bids 0..4607 = GEMM1 tiles + 1-in-9
// w2 converters (R13 layout); bids 4608..6655 = GEMM2 tiles that acquire-spin
// on per-(e,bm) counters released by GEMM1 CTAs (cutlass-semaphore pattern).
// Removes the inter-GEMM kernel boundary (tail/head overlap). Prepass (x+w1)
// unchanged from R13 and also resets the counters (no extra launch).
// ============================================================================

namespace {
constexpr int E_ = 8;
constexpr int T_ = 2048;
constexpr int D_ = 2048;
constexpr int F_ = 4096;

constexpr int BM = 128, BN = 128, BK = 64;
constexpr int NT = D_ / BK;                   // 32 k-tiles (K=2048 both GEMMs)

constexpr int BPITCH = 272;
constexpr int A_STAGE_B = BM * BK * 2;        // 16384 B
constexpr int B_STAGE_B = BK * BPITCH;        // 17408 B
constexpr int STAGE_B   = A_STAGE_B + B_STAGE_B;    // 33792
constexpr int SMEM_BYTES = 3 * STAGE_B + 128;       // ~99.1 KB -> 2 CTAs/SM

constexpr int N_G1   = 4096;                  // GEMM1 tiles (32 x 16 x 8)
constexpr int N_CVT  = 512;                   // w2 converter CTAs (1-in-9)
constexpr int G1_SPAN = N_G1 + N_CVT;         // 4608
constexpr int N_G2   = 2048;                  // GEMM2 tiles (16 x 16 x 8)
constexpr int CVT_T  = N_CVT * 256;

constexpr int NW24 = E_ * D_ * D_ / 4;        // float4 count of w2

constexpr float ALPHA_ = 1.702f;
constexpr float LIMIT_ = 7.0f;
}

// scratch (no allocations allowed)
__device__ __half g_acth[(size_t)E_ * T_ * D_];
__device__ __half g_xh  [(size_t)E_ * T_ * D_];
__device__ __half g_w1h [(size_t)E_ * D_ * F_];
__device__ __half g_w2h [(size_t)E_ * D_ * D_];
__device__ uint32_t g_actcnt[E_ * (T_ / BM)];   // 128 counters, 32 arrivals each
__device__ uint32_t g_w2cnt[1];                 // 512 arrivals

// ---------------- PTX helpers ----------------
__device__ __forceinline__ uint32_t smem_u32(const void* p) {
    uint32_t a;
    asm("{ .reg .u64 t; cvta.to.shared.u64 t, %1; cvt.u32.u64 %0, t; }" : "=r"(a) : "l"(p));
    return a;
}
__device__ __forceinline__ uint32_t swzA(uint32_t row, uint32_t ch) {
    return row * 128u + ((ch ^ (row & 7u)) * 16u);
}
__device__ __forceinline__ void cpasync16(uint32_t dst, const void* src) {
    asm volatile("cp.async.cg.shared.global [%0], [%1], 16;" :: "r"(dst), "l"(src) : "memory");
}
__device__ __forceinline__ void cpasync_arrive(uint32_t bar) {
    asm volatile("cp.async.mbarrier.arrive.noinc.shared::cta.b64 [%0];" :: "r"(bar) : "memory");
}
__device__ __forceinline__ void mbar_init(uint32_t bar, uint32_t cnt) {
    asm volatile("mbarrier.init.shared.b64 [%0], %1;" :: "r"(bar), "r"(cnt) : "memory");
}
__device__ __forceinline__ void mbar_arrive(uint32_t bar) {
    asm volatile("mbarrier.arrive.shared.b64 _, [%0];" :: "r"(bar) : "memory");
}
__device__ __forceinline__ void mbar_wait(uint32_t bar, uint32_t parity) {
    uint32_t done;
    asm volatile(
        "{\n\t.reg .pred p;\n\t"
        "mbarrier.try_wait.parity.acquire.cta.shared::cta.b64 p, [%1], %2;\n\t"
        "selp.b32 %0, 1, 0, p;\n\t}"
        : "=r"(done) : "r"(bar), "r"(parity) : "memory");
    if (!done) {
        asm volatile(
            "{\n\t.reg .pred P1;\n\t"
            "W_%=:\n\t"
            "mbarrier.try_wait.parity.acquire.cta.shared::cta.b64 P1, [%0], %1, 0x989680;\n\t"
            "@P1 bra.uni DN_%=;\n\t"
            "bra.uni W_%=;\n\t"
            "DN_%=:\n\t}"
            :: "r"(bar), "r"(parity) : "memory");
    }
}
__device__ __forceinline__ void ldsm_x4(uint32_t* r, uint32_t addr) {
    asm volatile("ldmatrix.sync.aligned.m8n8.x4.shared.b16 {%0,%1,%2,%3}, [%4];"
                 : "=r"(r[0]), "=r"(r[1]), "=r"(r[2]), "=r"(r[3]) : "r"(addr));
}
__device__ __forceinline__ void ldsm_x4_t(uint32_t* r, uint32_t addr) {
    asm volatile("ldmatrix.sync.aligned.m8n8.x4.trans.shared.b16 {%0,%1,%2,%3}, [%4];"
                 : "=r"(r[0]), "=r"(r[1]), "=r"(r[2]), "=r"(r[3]) : "r"(addr));
}
__device__ __forceinline__ void mma_f16(float* c, const uint32_t* a, const uint32_t* b) {
    asm volatile(
        "mma.sync.aligned.m16n8k16.row.col.f32.f16.f16.f32 "
        "{%0,%1,%2,%3}, {%4,%5,%6,%7}, {%8,%9}, {%0,%1,%2,%3};"
        : "+f"(c[0]), "+f"(c[1]), "+f"(c[2]), "+f"(c[3])
        : "r"(a[0]), "r"(a[1]), "r"(a[2]), "r"(a[3]), "r"(b[0]), "r"(b[1]));
}
__device__ __forceinline__ uint2 f4_to_h4(float4 v) {
    __half2 h0 = __floats2half2_rn(v.x, v.y);
    __half2 h1 = __floats2half2_rn(v.z, v.w);
    uint2 u;
    u.x = *reinterpret_cast<uint32_t*>(&h0);
    u.y = *reinterpret_cast<uint32_t*>(&h1);
    return u;
}
__device__ __forceinline__ void red_release_add1(uint32_t* p) {
    asm volatile("red.release.gpu.global.add.u32 [%0], %1;" :: "l"(p), "r"(1u) : "memory");
}
__device__ __forceinline__ uint32_t ld_acquire(const uint32_t* p) {
    uint32_t v;
    asm volatile("ld.acquire.gpu.global.u32 %0, [%1];" : "=r"(v) : "l"(p) : "memory");
    return v;
}

// ---------------- pre-pass: fp32 -> fp16(rn) for x + w1; resets counters ----
__global__ void to_half_xw1(const float4* __restrict__ x,
                            const float4* __restrict__ w1,
                            uint2* __restrict__ xh,
                            uint2* __restrict__ w1h,
                            int nx, int nw1,
                            uint32_t* __restrict__ actcnt,
                            uint32_t* __restrict__ w2cnt)
{
    if (blockIdx.x == 0) {
        if (threadIdx.x < E_ * (T_ / BM)) actcnt[threadIdx.x] = 0;
        if (threadIdx.x == 255) w2cnt[0] = 0;
    }
    const int total = nx + nw1;
    const int stride = gridDim.x * blockDim.x;
    int i = blockIdx.x * blockDim.x + threadIdx.x;
    auto one = [&](int j) {
        float4 v; uint2* d;
        if (j < nx) { v = x[j]; d = xh + j; }
        else        { v = w1[j - nx]; d = w1h + (j - nx); }
        *d = f4_to_h4(v);
    };
    #pragma unroll 1
    for (; i + 3 * stride < total; i += 4 * stride) {
        one(i); one(i + stride); one(i + 2 * stride); one(i + 3 * stride);
    }
    for (; i < total; i += stride) one(i);
}

// ----------------------------------------------------------------------------
// Fused kernel: GEMM1 tiles + w2 converters + GEMM2 tiles in one grid.
// ----------------------------------------------------------------------------
__global__ __launch_bounds__(256, 2)
void fused_mlp_kernel(const __half* __restrict__ xh,
                      const __half* __restrict__ w1h,
                      const float* __restrict__ b1g,
                      __half* __restrict__ acth,
                      const __half* __restrict__ w2h,
                      const float* __restrict__ b2g,
                      float* __restrict__ outg,
                      const float4* __restrict__ w2src,
                      uint2* __restrict__ w2dst,
                      uint32_t* __restrict__ actcnt,
                      uint32_t* __restrict__ w2cnt)
{
    extern __shared__ float dsm[];
    __shared__ __align__(8) uint64_t mbars[6];

    const int tid = threadIdx.x;
    const int cid = blockIdx.x;

    int e, byi, bxi, NTOT;
    bool fuse;
    const __half *Ag, *Wg;
    const float* biasv;

    if (cid < G1_SPAN) {
        const uint32_t q = (uint32_t)cid / 9u, r = (uint32_t)cid - q * 9u;
        if (r == 8u) {
            // -------- w2 converter CTA (q = 0..511) --------
            const int gtid = (int)q * 256 + tid;
            int i = gtid;
            #pragma unroll 1
            for (; i + 3 * CVT_T < NW24; i += 4 * CVT_T) {
                float4 v0 = w2src[i];
                float4 v1 = w2src[i + CVT_T];
                float4 v2 = w2src[i + 2 * CVT_T];
                float4 v3 = w2src[i + 3 * CVT_T];
                w2dst[i]             = f4_to_h4(v0);
                w2dst[i + CVT_T]     = f4_to_h4(v1);
                w2dst[i + 2 * CVT_T] = f4_to_h4(v2);
                w2dst[i + 3 * CVT_T] = f4_to_h4(v3);
            }
            for (; i < NW24; i += CVT_T) w2dst[i] = f4_to_h4(w2src[i]);
            __syncthreads();
            if (tid == 0) red_release_add1(w2cnt);
            return;
        }
        const uint32_t id = q * 8u + r;          // 0..4095
        e   = (int)(id >> 9);
        byi = (int)((id >> 5) & 15u);
        bxi = (int)(id & 31u);
        fuse = true; NTOT = F_;
        Ag = xh; Wg = w1h; biasv = b1g;
    } else {
        const uint32_t id2 = (uint32_t)(cid - G1_SPAN);  // 0..2047
        e   = (int)(id2 >> 8);
        byi = (int)((id2 >> 4) & 15u);
        bxi = (int)(id2 & 15u);
        fuse = false; NTOT = D_;
        Ag = acth; Wg = w2h; biasv = b2g;
    }

    const int wid  = tid >> 5;
    const int lane = tid & 31;
    const int bm = byi * BM;
    const int bn = bxi * BN;

    const __half* Ae = Ag + ((size_t)e * T_ + bm) * D_;
    const __half* We = Wg + (size_t)e * D_ * NTOT + bn;
    const float*  Be = biasv + (size_t)e * NTOT + bn;

    const uint32_t s0 = (smem_u32(dsm) + 127u) & ~127u;
    const uint32_t mb = smem_u32(mbars);
    const uint32_t fb0 = mb,      fb1 = mb + 8,  fb2 = mb + 16;
    const uint32_t eb0 = mb + 24, eb1 = mb + 32, eb2 = mb + 40;

    if (tid == 0) {
        mbar_init(fb0, 256); mbar_init(fb1, 256); mbar_init(fb2, 256);
        mbar_init(eb0, 256); mbar_init(eb1, 256); mbar_init(eb2, 256);
        if (!fuse) {
            // GEMM2: wait for all 32 producers of act rows [e, bm..bm+128)
            // and for the whole w2 conversion (512 converter arrivals).
            const uint32_t* ac = actcnt + (e * 16 + byi);
            while (ld_acquire(ac) < 32u) __nanosleep(128);
            while (ld_acquire(w2cnt) < (uint32_t)N_CVT) __nanosleep(128);
        }
    }
    __syncthreads();

    // --- producer state ---
    const int pArow = tid >> 3, pAc = tid & 7;
    const uint32_t pAoff = swzA(pArow, pAc);
    const uint32_t pAg   = (uint32_t)pArow * D_ + pAc * 8;
    const int pBk = tid >> 4, pBc = tid & 15;
    const uint32_t pBoff = (uint32_t)pBk * BPITCH + pBc * 16;
    const uint32_t pBg   = (uint32_t)pBk * NTOT + pBc * 8;

    const __half* aSrc = Ae;
    const __half* bSrc = We;
    auto produce = [&](uint32_t base, uint32_t fbar) {
        #pragma unroll
        for (int i = 0; i < 4; i++)
            cpasync16(base + pAoff + i * (32u * 128u),
                      aSrc + pAg + (size_t)(32 * i) * D_);
        const uint32_t pb = base + A_STAGE_B;
        #pragma unroll
        for (int i = 0; i < 4; i++)
            cpasync16(pb + pBoff + i * (16u * BPITCH),
                      bSrc + pBg + (size_t)(16 * i) * NTOT);
        cpasync_arrive(fbar);
        aSrc += BK;
        bSrc += (size_t)BK * NTOT;
    };

    const int wm = (wid >> 2) * 64;
    const int wn = (wid & 3) * 32;

    float acc[4][4][4];
    #pragma unroll
    for (int mi = 0; mi < 4; mi++)
        #pragma unroll
        for (int ni = 0; ni < 4; ni++)
            #pragma unroll
            for (int v = 0; v < 4; v++) acc[mi][ni][v] = 0.0f;

    const int lrow = lane & 15;
    const int lchx = lane >> 4;
    const uint32_t rx = (uint32_t)(lrow & 7);
    uint32_t aRowOff[4];
    #pragma unroll
    for (int mi = 0; mi < 4; mi++)
        aRowOff[mi] = (uint32_t)(wm + mi * 16 + lrow) * 128u;
    const uint32_t bLaneOff = (uint32_t)(lane & 15) * BPITCH
                            + (uint32_t)((wn >> 3) + (lane >> 4)) * 16u;

    auto consume = [&](uint32_t sA) {
        const uint32_t sBl = sA + A_STAGE_B + bLaneOff;
        uint32_t b[2][4][2];
        {
            uint32_t r[4];
            ldsm_x4_t(r, sBl);
            b[0][0][0]=r[0]; b[0][0][1]=r[1]; b[0][1][0]=r[2]; b[0][1][1]=r[3];
            ldsm_x4_t(r, sBl + 32u);
            b[0][2][0]=r[0]; b[0][2][1]=r[1]; b[0][3][0]=r[2]; b[0][3][1]=r[3];
        }
        #pragma unroll
        for (int ks = 0; ks < 4; ks++) {
            uint32_t a[4][4];
            #pragma unroll
            for (int mi = 0; mi < 4; mi++) {
                uint32_t ch = ((uint32_t)(2 * ks + lchx) ^ rx) * 16u;
                ldsm_x4(a[mi], sA + aRowOff[mi] + ch);
            }
            if (ks < 3) {
                const uint32_t nb = sBl + (uint32_t)(ks + 1) * (16u * BPITCH);
                uint32_t r[4];
                ldsm_x4_t(r, nb);
                b[(ks+1)&1][0][0]=r[0]; b[(ks+1)&1][0][1]=r[1];
                b[(ks+1)&1][1][0]=r[2]; b[(ks+1)&1][1][1]=r[3];
                ldsm_x4_t(r, nb + 32u);
                b[(ks+1)&1][2][0]=r[0]; b[(ks+1)&1][2][1]=r[1];
                b[(ks+1)&1][3][0]=r[2]; b[(ks+1)&1][3][1]=r[3];
            }
            #pragma unroll
            for (int mi = 0; mi < 4; mi++)
                #pragma unroll
                for (int ni = 0; ni < 4; ni++)
                    mma_f16(acc[mi][ni], a[mi], b[ks & 1][ni]);
        }
    };

    const uint32_t st0 = s0, st1 = s0 + STAGE_B, st2 = s0 + 2 * STAGE_B;

    uint32_t ep0 = 1, ep1 = 1, ep2 = 1;
    uint32_t fp0 = 0, fp1 = 0, fp2 = 0;

    mbar_wait(eb0, ep0); ep0 ^= 1; produce(st0, fb0);
    mbar_wait(eb1, ep1); ep1 ^= 1; produce(st1, fb1);

    #pragma unroll 1
    for (int r = 0; r < NT / 3; r++) {
        mbar_wait(eb2, ep2); ep2 ^= 1; produce(st2, fb2);
        mbar_wait(fb0, fp0); fp0 ^= 1; consume(st0); mbar_arrive(eb0);
        mbar_wait(eb0, ep0); ep0 ^= 1; produce(st0, fb0);
        mbar_wait(fb1, fp1); fp1 ^= 1; consume(st1); mbar_arrive(eb1);
        mbar_wait(eb1, ep1); ep1 ^= 1; produce(st1, fb1);
        mbar_wait(fb2, fp2); fp2 ^= 1; consume(st2); mbar_arrive(eb2);
    }
    mbar_wait(fb0, fp0); consume(st0);
    mbar_wait(fb1, fp1); consume(st1);

    // ------------------------------ epilogue ------------------------------
    #pragma unroll
    for (int ni = 0; ni < 4; ni++) {
        const int cl = wn + ni * 8 + 2 * (lane & 3);
        const float b_e = Be[cl];
        const float b_o = Be[cl + 1];
        #pragma unroll
        for (int mi = 0; mi < 4; mi++) {
            const int r0 = bm + wm + mi * 16 + (lane >> 2);
            #pragma unroll
            for (int h = 0; h < 2; h++) {
                const float v0 = acc[mi][ni][2 * h + 0] + b_e;
                const float v1 = acc[mi][ni][2 * h + 1] + b_o;
                const size_t row = (size_t)e * T_ + r0 + 8 * h;
                if (fuse) {
                    float g = fminf(v0, LIMIT_);
                    float l = fminf(fmaxf(v1, -LIMIT_), LIMIT_);
                    float sg = 1.0f / (1.0f + __expf(-ALPHA_ * g));
                    acth[row * D_ + ((bn + cl) >> 1)] =
                        __float2half_rn(g * sg * (l + 1.0f));
                } else {
                    float2 o = make_float2(v0, v1);
                    *(float2*)(outg + row * D_ + bn + cl) = o;
                }
            }
        }
    }

    if (fuse) {
        // signal: this CTA's slice of act rows [e, bm..bm+128) is written
        __syncthreads();
        if (tid == 0) red_release_add1(actcnt + (e * 16 + byi));
    }
}

// ----------------------------------------------------------------------------
extern "C" void kernel_launch(void* const* d_in, const int* in_sizes, int n_in,
                              void* d_out, int out_size)
{
    (void)in_sizes; (void)n_in; (void)out_size;
    const float* x  = (const float*)d_in[0];
    const float* w1 = (const float*)d_in[1];
    const float* b1 = (const float*)d_in[2];
    const float* w2 = (const float*)d_in[3];
    const float* b2 = (const float*)d_in[4];
    float* out = (float*)d_out;

    __half *acth, *xh, *w1h, *w2h;
    uint32_t *actcnt, *w2cnt;
    cudaGetSymbolAddress((void**)&acth,   g_acth);
    cudaGetSymbolAddress((void**)&xh,     g_xh);
    cudaGetSymbolAddress((void**)&w1h,    g_w1h);
    cudaGetSymbolAddress((void**)&w2h,    g_w2h);
    cudaGetSymbolAddress((void**)&actcnt, g_actcnt);
    cudaGetSymbolAddress((void**)&w2cnt,  g_w2cnt);

    static bool attr_done = false;
    if (!attr_done) {
        cudaFuncSetAttribute(fused_mlp_kernel,
                             cudaFuncAttributeMaxDynamicSharedMemorySize, SMEM_BYTES);
        attr_done = true;
    }

    const int nx  = E_ * T_ * D_ / 4;
    const int nw1 = E_ * D_ * F_ / 4;

    // pre-pass: x + w1 conversion; also resets the dependency counters
    to_half_xw1<<<4096, 256>>>((const float4*)x, (const float4*)w1,
                               (uint2*)xh, (uint2*)w1h, nx, nw1, actcnt, w2cnt);

    // fused GEMM1 + w2-convert + GEMM2 (flag-synchronized)
    fused_mlp_kernel<<<G1_SPAN + N_G2, 256, SMEM_BYTES>>>(
        xh, w1h, b1, acth, w2h, b2, out,
        (const float4*)w2, (uint2*)w2h, actcnt, w2cnt);
}